// round 1
// baseline (speedup 1.0000x reference)
#include <cuda_runtime.h>

#define NN 50000
#define EE 800000
#define FF 602
#define HH 32
#define CC 41
#define BN_EPS 1e-5f
#define FULLMASK 0xffffffffu

// ---------------- scratch (device globals; no allocation allowed) ----------
static __device__ float d_y  [NN * HH];   // x @ W1a
static __device__ float d_agg[NN * HH];   // edge aggregation buffer (reused)
static __device__ float d_h1 [NN * HH];   // conv1 pre-BN
static __device__ float d_h  [NN * HH];   // conv1 post-BN
static __device__ float d_h2 [NN * HH];   // conv2 pre-BN
static __device__ float d_stats[4 * HH];  // sum1, sumsq1, sum2, sumsq2

// ---------------- K1: y[N,32] = x[N,602] @ W1a[602,32] ---------------------
// 77KB dynamic smem for W; each warp computes 4 consecutive rows,
// lane = output column; x values broadcast via shfl.
__global__ void k_gemm1(const float* __restrict__ x, const float* __restrict__ W1a) {
    extern __shared__ float Ws[];  // FF*HH floats
    for (int i = threadIdx.x; i < FF * HH; i += blockDim.x) Ws[i] = W1a[i];
    __syncthreads();

    const int lane = threadIdx.x & 31;
    const int gw   = (blockIdx.x * blockDim.x + threadIdx.x) >> 5;
    const int r0   = gw * 4;
    if (r0 >= NN) return;

    const bool v1 = (r0 + 1) < NN, v2 = (r0 + 2) < NN, v3 = (r0 + 3) < NN;
    const float* x0 = x + (size_t)r0 * FF;

    float acc0 = 0.f, acc1 = 0.f, acc2 = 0.f, acc3 = 0.f;

    constexpr int KB_MAIN = (FF / 32) * 32;  // 576
    int kb = 0;
    for (; kb < KB_MAIN; kb += 32) {
        float xv0 = x0[kb + lane];
        float xv1 = v1 ? x0[1 * FF + kb + lane] : 0.f;
        float xv2 = v2 ? x0[2 * FF + kb + lane] : 0.f;
        float xv3 = v3 ? x0[3 * FF + kb + lane] : 0.f;
#pragma unroll
        for (int j = 0; j < 32; j++) {
            float w = Ws[(kb + j) * HH + lane];
            acc0 += __shfl_sync(FULLMASK, xv0, j) * w;
            acc1 += __shfl_sync(FULLMASK, xv1, j) * w;
            acc2 += __shfl_sync(FULLMASK, xv2, j) * w;
            acc3 += __shfl_sync(FULLMASK, xv3, j) * w;
        }
    }
    {   // tail: 602 - 576 = 26
        constexpr int REM = FF - KB_MAIN;
        float xv0 = (lane < REM) ? x0[kb + lane] : 0.f;
        float xv1 = (v1 && lane < REM) ? x0[1 * FF + kb + lane] : 0.f;
        float xv2 = (v2 && lane < REM) ? x0[2 * FF + kb + lane] : 0.f;
        float xv3 = (v3 && lane < REM) ? x0[3 * FF + kb + lane] : 0.f;
#pragma unroll
        for (int j = 0; j < REM; j++) {
            float w = Ws[(kb + j) * HH + lane];
            acc0 += __shfl_sync(FULLMASK, xv0, j) * w;
            acc1 += __shfl_sync(FULLMASK, xv1, j) * w;
            acc2 += __shfl_sync(FULLMASK, xv2, j) * w;
            acc3 += __shfl_sync(FULLMASK, xv3, j) * w;
        }
    }
    d_y[(size_t)r0 * HH + lane] = acc0;
    if (v1) d_y[(size_t)(r0 + 1) * HH + lane] = acc1;
    if (v2) d_y[(size_t)(r0 + 2) * HH + lane] = acc2;
    if (v3) d_y[(size_t)(r0 + 3) * HH + lane] = acc3;
}

// ---------------- K2: edge aggregation: dst[row[e]] += src[col[e]] ---------
// warp per edge, lane per feature.
__global__ void k_edges(const int* __restrict__ row, const int* __restrict__ col,
                        const float* __restrict__ src, float* __restrict__ dst) {
    unsigned idx = blockIdx.x * 256u + threadIdx.x;
    unsigned e   = idx >> 5;
    if (e >= EE) return;
    const int lane = threadIdx.x & 31;
    int r = row[e];
    int c = col[e];
    atomicAdd(dst + (size_t)r * HH + lane, src[(size_t)c * HH + lane]);
}

// ---------------- K3: conv1 tail: h1 = relu(y+agg+b1a) @ W1b + b1b + stats -
__global__ void k_mlp1(const float* __restrict__ a, const float* __restrict__ b,
                       const float* __restrict__ ba, const float* __restrict__ Wb,
                       const float* __restrict__ bb, float* __restrict__ outp,
                       float* __restrict__ stats) {
    __shared__ float Wsb[HH * HH];
    for (int i = threadIdx.x; i < HH * HH; i += blockDim.x) Wsb[i] = Wb[i];
    __syncthreads();

    const int lane = threadIdx.x & 31;
    const int gw   = (blockIdx.x * blockDim.x + threadIdx.x) >> 5;
    const int nw   = (gridDim.x * blockDim.x) >> 5;
    const float baL = ba[lane], bbL = bb[lane];

    float s = 0.f, sq = 0.f;
    for (int r = gw; r < NN; r += nw) {
        float z = a[(size_t)r * HH + lane] + b[(size_t)r * HH + lane] + baL;
        z = fmaxf(z, 0.f);
        float acc = bbL;
#pragma unroll
        for (int j = 0; j < HH; j++)
            acc += __shfl_sync(FULLMASK, z, j) * Wsb[j * HH + lane];
        outp[(size_t)r * HH + lane] = acc;
        s += acc; sq += acc * acc;
    }
    atomicAdd(&stats[lane],      s);
    atomicAdd(&stats[HH + lane], sq);
}

// ---------------- K5: BN apply -----------------------------------------------
__global__ void k_bn(const float* __restrict__ in, const float* __restrict__ g,
                     const float* __restrict__ be, const float* __restrict__ stats,
                     float* __restrict__ outp) {
    int idx = blockIdx.x * 256 + threadIdx.x;
    if (idx >= NN * HH) return;
    int f = idx & (HH - 1);
    float m = stats[f] * (1.f / NN);
    float v = stats[HH + f] * (1.f / NN) - m * m;
    float scale = g[f] * rsqrtf(v + BN_EPS);
    float shift = be[f] - m * scale;
    outp[idx] = in[idx] * scale + shift;
}

// ---------------- K7: conv2 full MLP: h2 = relu((h+agg)@W2a+b2a)@W2b+b2b ---
__global__ void k_mlp2(const float* __restrict__ a, const float* __restrict__ b,
                       const float* __restrict__ Wa, const float* __restrict__ ba,
                       const float* __restrict__ Wb, const float* __restrict__ bb,
                       float* __restrict__ outp, float* __restrict__ stats) {
    __shared__ float Wsa[HH * HH];
    __shared__ float Wsb[HH * HH];
    for (int i = threadIdx.x; i < HH * HH; i += blockDim.x) { Wsa[i] = Wa[i]; Wsb[i] = Wb[i]; }
    __syncthreads();

    const int lane = threadIdx.x & 31;
    const int gw   = (blockIdx.x * blockDim.x + threadIdx.x) >> 5;
    const int nw   = (gridDim.x * blockDim.x) >> 5;
    const float baL = ba[lane], bbL = bb[lane];

    float s = 0.f, sq = 0.f;
    for (int r = gw; r < NN; r += nw) {
        float t = a[(size_t)r * HH + lane] + b[(size_t)r * HH + lane];
        float u = baL;
#pragma unroll
        for (int j = 0; j < HH; j++)
            u += __shfl_sync(FULLMASK, t, j) * Wsa[j * HH + lane];
        u = fmaxf(u, 0.f);
        float acc = bbL;
#pragma unroll
        for (int j = 0; j < HH; j++)
            acc += __shfl_sync(FULLMASK, u, j) * Wsb[j * HH + lane];
        outp[(size_t)r * HH + lane] = acc;
        s += acc; sq += acc * acc;
    }
    atomicAdd(&stats[lane],      s);
    atomicAdd(&stats[HH + lane], sq);
}

// ---------------- K9: head: out = relu(bn2(h2)@Wf1+bf1)@Wf2+bf2 ------------
__global__ void k_head(const float* __restrict__ Wf1, const float* __restrict__ bf1,
                       const float* __restrict__ Wf2, const float* __restrict__ bf2,
                       const float* __restrict__ g2, const float* __restrict__ be2,
                       float* __restrict__ outp) {
    __shared__ float Ws1[HH * HH];
    __shared__ float Ws2[HH * CC];
    for (int i = threadIdx.x; i < HH * HH; i += blockDim.x) Ws1[i] = Wf1[i];
    for (int i = threadIdx.x; i < HH * CC; i += blockDim.x) Ws2[i] = Wf2[i];
    __syncthreads();

    const int lane = threadIdx.x & 31;
    const int gw   = (blockIdx.x * blockDim.x + threadIdx.x) >> 5;
    const int nw   = (gridDim.x * blockDim.x) >> 5;

    float m = d_stats[2 * HH + lane] * (1.f / NN);
    float v = d_stats[3 * HH + lane] * (1.f / NN) - m * m;
    float scale = g2[lane] * rsqrtf(v + BN_EPS);
    float shift = be2[lane] - m * scale;

    const float bf1L = bf1[lane];
    const float b0 = bf2[lane];
    const float b1 = (lane < CC - HH) ? bf2[lane + HH] : 0.f;

    for (int r = gw; r < NN; r += nw) {
        float gv = d_h2[(size_t)r * HH + lane] * scale + shift;
        float z = bf1L;
#pragma unroll
        for (int j = 0; j < HH; j++)
            z += __shfl_sync(FULLMASK, gv, j) * Ws1[j * HH + lane];
        z = fmaxf(z, 0.f);

        float a0 = b0, a1 = b1;
#pragma unroll
        for (int j = 0; j < HH; j++) {
            float zj = __shfl_sync(FULLMASK, z, j);
            a0 += zj * Ws2[j * CC + lane];
            if (lane < CC - HH) a1 += zj * Ws2[j * CC + lane + HH];
        }
        outp[(size_t)r * CC + lane] = a0;
        if (lane < CC - HH) outp[(size_t)r * CC + lane + HH] = a1;
    }
}

// ---------------- launcher --------------------------------------------------
extern "C" void kernel_launch(void* const* d_in, const int* in_sizes, int n_in,
                              void* d_out, int out_size) {
    const float* x   = (const float*)d_in[0];
    const int*   row = (const int*)  d_in[1];
    const int*   col = (const int*)  d_in[2];
    const float* W1a = (const float*)d_in[3];
    const float* b1a = (const float*)d_in[4];
    const float* W1b = (const float*)d_in[5];
    const float* b1b = (const float*)d_in[6];
    const float* g1  = (const float*)d_in[7];
    const float* be1 = (const float*)d_in[8];
    const float* W2a = (const float*)d_in[9];
    const float* b2a = (const float*)d_in[10];
    const float* W2b = (const float*)d_in[11];
    const float* b2b = (const float*)d_in[12];
    const float* g2  = (const float*)d_in[13];
    const float* be2 = (const float*)d_in[14];
    const float* Wf1 = (const float*)d_in[15];
    const float* bf1 = (const float*)d_in[16];
    const float* Wf2 = (const float*)d_in[17];
    const float* bf2 = (const float*)d_in[18];
    float* out = (float*)d_out;

    float *y, *agg, *h1, *h, *h2, *stats;
    cudaGetSymbolAddress((void**)&y,     d_y);
    cudaGetSymbolAddress((void**)&agg,   d_agg);
    cudaGetSymbolAddress((void**)&h1,    d_h1);
    cudaGetSymbolAddress((void**)&h,     d_h);
    cudaGetSymbolAddress((void**)&h2,    d_h2);
    cudaGetSymbolAddress((void**)&stats, d_stats);

    // zero aggregation buffer + BN statistics
    cudaMemsetAsync(agg,   0, sizeof(float) * NN * HH, 0);
    cudaMemsetAsync(stats, 0, sizeof(float) * 4 * HH, 0);

    // K1: y = x @ W1a   (pushed ahead of aggregation by linearity)
    cudaFuncSetAttribute(k_gemm1, cudaFuncAttributeMaxDynamicSharedMemorySize,
                         FF * HH * (int)sizeof(float));
    {
        int warps  = (NN + 3) / 4;
        int blocks = (warps + 7) / 8;
        k_gemm1<<<blocks, 256, FF * HH * sizeof(float), 0>>>(x, W1a);
    }

    const int eblocks = (EE * 32 + 255) / 256;

    // conv1: agg(y) -> mlp tail -> BN
    k_edges<<<eblocks, 256, 0, 0>>>(row, col, y, agg);
    k_mlp1<<<400, 256, 0, 0>>>(y, agg, b1a, W1b, b1b, h1, stats);
    k_bn<<<(NN * HH + 255) / 256, 256, 0, 0>>>(h1, g1, be1, stats, h);

    // conv2: agg(h) -> full mlp -> (BN folded into head)
    cudaMemsetAsync(agg, 0, sizeof(float) * NN * HH, 0);
    k_edges<<<eblocks, 256, 0, 0>>>(row, col, h, agg);
    k_mlp2<<<400, 256, 0, 0>>>(h, agg, W2a, b2a, W2b, b2b, h2, stats + 2 * HH);

    // head: BN2 + relu(g@Wf1+bf1)@Wf2+bf2
    k_head<<<400, 256, 0, 0>>>(Wf1, bf1, Wf2, bf2, g2, be2, out);
}

// round 2
// speedup vs baseline: 1.3279x; 1.3279x over previous
#include <cuda_runtime.h>

#define NN 50000
#define EE 800000
#define FF 602
#define HH 32
#define CC 41
#define BN_EPS 1e-5f
#define FULLMASK 0xffffffffu

// ---------------- scratch (device globals) ----------------------------------
static __device__ float d_y  [NN * HH];   // x @ W1a
static __device__ float d_h1 [NN * HH];   // conv1 pre-BN
static __device__ float d_h2 [NN * HH];   // conv2 pre-BN
static __device__ float d_stats[4 * HH];  // sum1, sumsq1, sum2, sumsq2
static __device__ int   d_counts[NN];
static __device__ int   d_rowptr[NN];
static __device__ int   d_cursor[NN];
static __device__ int   d_colsorted[EE];
static __device__ int   d_bsum[256];
static __device__ int   d_boff[256];

#define NB_SCAN ((NN + 255) / 256)   // 196

// ---------------- K1: y[N,32] = x[N,602] @ W1a[602,32] ---------------------
__global__ void k_gemm1(const float* __restrict__ x, const float* __restrict__ W1a) {
    extern __shared__ float Ws[];  // FF*HH floats
    for (int i = threadIdx.x; i < FF * HH; i += blockDim.x) Ws[i] = W1a[i];
    __syncthreads();

    const int lane = threadIdx.x & 31;
    const int gw   = (blockIdx.x * blockDim.x + threadIdx.x) >> 5;
    const int r0   = gw * 4;
    if (r0 >= NN) return;

    const bool v1 = (r0 + 1) < NN, v2 = (r0 + 2) < NN, v3 = (r0 + 3) < NN;
    const float* x0 = x + (size_t)r0 * FF;

    float acc0 = 0.f, acc1 = 0.f, acc2 = 0.f, acc3 = 0.f;

    constexpr int KB_MAIN = (FF / 32) * 32;  // 576
    int kb = 0;
    for (; kb < KB_MAIN; kb += 32) {
        float xv0 = x0[kb + lane];
        float xv1 = v1 ? x0[1 * FF + kb + lane] : 0.f;
        float xv2 = v2 ? x0[2 * FF + kb + lane] : 0.f;
        float xv3 = v3 ? x0[3 * FF + kb + lane] : 0.f;
#pragma unroll
        for (int j = 0; j < 32; j++) {
            float w = Ws[(kb + j) * HH + lane];
            acc0 += __shfl_sync(FULLMASK, xv0, j) * w;
            acc1 += __shfl_sync(FULLMASK, xv1, j) * w;
            acc2 += __shfl_sync(FULLMASK, xv2, j) * w;
            acc3 += __shfl_sync(FULLMASK, xv3, j) * w;
        }
    }
    {   // tail: 602 - 576 = 26
        constexpr int REM = FF - KB_MAIN;
        float xv0 = (lane < REM) ? x0[kb + lane] : 0.f;
        float xv1 = (v1 && lane < REM) ? x0[1 * FF + kb + lane] : 0.f;
        float xv2 = (v2 && lane < REM) ? x0[2 * FF + kb + lane] : 0.f;
        float xv3 = (v3 && lane < REM) ? x0[3 * FF + kb + lane] : 0.f;
#pragma unroll
        for (int j = 0; j < REM; j++) {
            float w = Ws[(kb + j) * HH + lane];
            acc0 += __shfl_sync(FULLMASK, xv0, j) * w;
            acc1 += __shfl_sync(FULLMASK, xv1, j) * w;
            acc2 += __shfl_sync(FULLMASK, xv2, j) * w;
            acc3 += __shfl_sync(FULLMASK, xv3, j) * w;
        }
    }
    d_y[(size_t)r0 * HH + lane] = acc0;
    if (v1) d_y[(size_t)(r0 + 1) * HH + lane] = acc1;
    if (v2) d_y[(size_t)(r0 + 2) * HH + lane] = acc2;
    if (v3) d_y[(size_t)(r0 + 3) * HH + lane] = acc3;
}

// ---------------- CSR build --------------------------------------------------
__global__ void k_hist(const int* __restrict__ row) {
    int e = blockIdx.x * 256 + threadIdx.x;
    if (e < EE) atomicAdd(&d_counts[row[e]], 1);
}

__global__ void k_scan1() {  // per-block sums of counts
    __shared__ int sh[256];
    int i = blockIdx.x * 256 + threadIdx.x;
    int v = (i < NN) ? d_counts[i] : 0;
    sh[threadIdx.x] = v;
    __syncthreads();
    for (int off = 128; off > 0; off >>= 1) {
        if (threadIdx.x < off) sh[threadIdx.x] += sh[threadIdx.x + off];
        __syncthreads();
    }
    if (threadIdx.x == 0) d_bsum[blockIdx.x] = sh[0];
}

__global__ void k_scan2() {  // exclusive scan of block sums (single block)
    __shared__ int sh[256];
    int tid = threadIdx.x;
    int v = (tid < NB_SCAN) ? d_bsum[tid] : 0;
    sh[tid] = v;
    __syncthreads();
    for (int off = 1; off < 256; off <<= 1) {
        int t = (tid >= off) ? sh[tid - off] : 0;
        __syncthreads();
        sh[tid] += t;
        __syncthreads();
    }
    if (tid < NB_SCAN) d_boff[tid] = sh[tid] - v;  // exclusive
}

__global__ void k_scan3() {  // per-element exclusive scan -> rowptr, cursor
    __shared__ int sh[256];
    int tid = threadIdx.x;
    int i = blockIdx.x * 256 + tid;
    int c = (i < NN) ? d_counts[i] : 0;
    sh[tid] = c;
    __syncthreads();
    for (int off = 1; off < 256; off <<= 1) {
        int t = (tid >= off) ? sh[tid - off] : 0;
        __syncthreads();
        sh[tid] += t;
        __syncthreads();
    }
    int start = d_boff[blockIdx.x] + sh[tid] - c;
    if (i < NN) { d_rowptr[i] = start; d_cursor[i] = start; }
}

__global__ void k_scatter(const int* __restrict__ row, const int* __restrict__ col) {
    int e = blockIdx.x * 256 + threadIdx.x;
    if (e >= EE) return;
    int r = row[e];
    int pos = atomicAdd(&d_cursor[r], 1);
    d_colsorted[pos] = col[e];
}

// ---------------- fused gather + MLP -----------------------------------------
// Warp per node: acc(lane) = sum_{c in nbrs(n)} src_bn(c,lane); then GIN MLP.

__device__ __forceinline__ float gather_sum(const float* __restrict__ src,
                                            int n, int lane,
                                            float scale, float shift) {
    int s0  = d_rowptr[n];
    int deg = d_counts[n];
    float acc = 0.f;
    for (int e0 = 0; e0 < deg; e0 += 32) {
        int rem = deg - e0;
        if (rem > 32) rem = 32;
        int idx = (lane < rem) ? d_colsorted[s0 + e0 + lane] : 0;
        int j = 0;
        for (; j + 4 <= rem; j += 4) {
            int c0 = __shfl_sync(FULLMASK, idx, j);
            int c1 = __shfl_sync(FULLMASK, idx, j + 1);
            int c2 = __shfl_sync(FULLMASK, idx, j + 2);
            int c3 = __shfl_sync(FULLMASK, idx, j + 3);
            float v0 = src[(size_t)c0 * HH + lane];
            float v1 = src[(size_t)c1 * HH + lane];
            float v2 = src[(size_t)c2 * HH + lane];
            float v3 = src[(size_t)c3 * HH + lane];
            acc += v0 * scale + shift;
            acc += v1 * scale + shift;
            acc += v2 * scale + shift;
            acc += v3 * scale + shift;
        }
        for (; j < rem; j++) {
            int c = __shfl_sync(FULLMASK, idx, j);
            acc += src[(size_t)c * HH + lane] * scale + shift;
        }
    }
    return acc;
}

// conv1: h1 = relu(y[n] + agg(y) + b1a) @ W1b + b1b ; accumulate stats1
__global__ void __launch_bounds__(1024) k_gin1(
    const float* __restrict__ ba, const float* __restrict__ Wb,
    const float* __restrict__ bb) {
    __shared__ float Wsb[HH * HH];
    __shared__ float red1[32][32];
    __shared__ float red2[32][32];
    for (int i = threadIdx.x; i < HH * HH; i += 1024) Wsb[i] = Wb[i];
    __syncthreads();

    const int lane = threadIdx.x & 31;
    const int warp = threadIdx.x >> 5;
    const int n = blockIdx.x * 32 + warp;

    float s = 0.f, sq = 0.f;
    if (n < NN) {
        float acc = gather_sum(d_y, n, lane, 1.f, 0.f);
        float z = d_y[(size_t)n * HH + lane] + acc + ba[lane];
        z = fmaxf(z, 0.f);
        float o = bb[lane];
#pragma unroll
        for (int j = 0; j < HH; j++)
            o += __shfl_sync(FULLMASK, z, j) * Wsb[j * HH + lane];
        d_h1[(size_t)n * HH + lane] = o;
        s = o; sq = o * o;
    }
    red1[warp][lane] = s;
    red2[warp][lane] = sq;
    __syncthreads();
    if (warp == 0) {
        float t1 = 0.f, t2 = 0.f;
#pragma unroll
        for (int w = 0; w < 32; w++) { t1 += red1[w][lane]; t2 += red2[w][lane]; }
        atomicAdd(&d_stats[lane],      t1);
        atomicAdd(&d_stats[HH + lane], t2);
    }
}

// conv2: reads h1 with BN1 folded in; h2 = relu((g+agg)@W2a+b2a)@W2b+b2b ; stats2
__global__ void __launch_bounds__(1024) k_gin2(
    const float* __restrict__ g1, const float* __restrict__ be1,
    const float* __restrict__ Wa, const float* __restrict__ ba,
    const float* __restrict__ Wb, const float* __restrict__ bb) {
    __shared__ float Wsa[HH * HH];
    __shared__ float Wsb[HH * HH];
    __shared__ float red1[32][32];
    __shared__ float red2[32][32];
    for (int i = threadIdx.x; i < HH * HH; i += 1024) { Wsa[i] = Wa[i]; Wsb[i] = Wb[i]; }
    __syncthreads();

    const int lane = threadIdx.x & 31;
    const int warp = threadIdx.x >> 5;
    const int n = blockIdx.x * 32 + warp;

    // BN1 scale/shift per feature (= lane)
    float m = d_stats[lane] * (1.f / NN);
    float v = d_stats[HH + lane] * (1.f / NN) - m * m;
    float scale = g1[lane] * rsqrtf(v + BN_EPS);
    float shift = be1[lane] - m * scale;

    float s = 0.f, sq = 0.f;
    if (n < NN) {
        float acc = gather_sum(d_h1, n, lane, scale, shift);
        float self = d_h1[(size_t)n * HH + lane] * scale + shift;
        float t = self + acc;
        float u = ba[lane];
#pragma unroll
        for (int j = 0; j < HH; j++)
            u += __shfl_sync(FULLMASK, t, j) * Wsa[j * HH + lane];
        u = fmaxf(u, 0.f);
        float o = bb[lane];
#pragma unroll
        for (int j = 0; j < HH; j++)
            o += __shfl_sync(FULLMASK, u, j) * Wsb[j * HH + lane];
        d_h2[(size_t)n * HH + lane] = o;
        s = o; sq = o * o;
    }
    red1[warp][lane] = s;
    red2[warp][lane] = sq;
    __syncthreads();
    if (warp == 0) {
        float t1 = 0.f, t2 = 0.f;
#pragma unroll
        for (int w = 0; w < 32; w++) { t1 += red1[w][lane]; t2 += red2[w][lane]; }
        atomicAdd(&d_stats[2 * HH + lane], t1);
        atomicAdd(&d_stats[3 * HH + lane], t2);
    }
}

// ---------------- head: out = relu(bn2(h2)@Wf1+bf1)@Wf2+bf2 ------------------
__global__ void k_head(const float* __restrict__ Wf1, const float* __restrict__ bf1,
                       const float* __restrict__ Wf2, const float* __restrict__ bf2,
                       const float* __restrict__ g2, const float* __restrict__ be2,
                       float* __restrict__ outp) {
    __shared__ float Ws1[HH * HH];
    __shared__ float Ws2[HH * CC];
    for (int i = threadIdx.x; i < HH * HH; i += blockDim.x) Ws1[i] = Wf1[i];
    for (int i = threadIdx.x; i < HH * CC; i += blockDim.x) Ws2[i] = Wf2[i];
    __syncthreads();

    const int lane = threadIdx.x & 31;
    const int gw   = (blockIdx.x * blockDim.x + threadIdx.x) >> 5;
    const int nw   = (gridDim.x * blockDim.x) >> 5;

    float m = d_stats[2 * HH + lane] * (1.f / NN);
    float v = d_stats[3 * HH + lane] * (1.f / NN) - m * m;
    float scale = g2[lane] * rsqrtf(v + BN_EPS);
    float shift = be2[lane] - m * scale;

    const float bf1L = bf1[lane];
    const float b0 = bf2[lane];
    const float b1 = (lane < CC - HH) ? bf2[lane + HH] : 0.f;

    for (int r = gw; r < NN; r += nw) {
        float gv = d_h2[(size_t)r * HH + lane] * scale + shift;
        float z = bf1L;
#pragma unroll
        for (int j = 0; j < HH; j++)
            z += __shfl_sync(FULLMASK, gv, j) * Ws1[j * HH + lane];
        z = fmaxf(z, 0.f);

        float a0 = b0, a1 = b1;
#pragma unroll
        for (int j = 0; j < HH; j++) {
            float zj = __shfl_sync(FULLMASK, z, j);
            a0 += zj * Ws2[j * CC + lane];
            if (lane < CC - HH) a1 += zj * Ws2[j * CC + lane + HH];
        }
        outp[(size_t)r * CC + lane] = a0;
        if (lane < CC - HH) outp[(size_t)r * CC + lane + HH] = a1;
    }
}

// ---------------- launcher ----------------------------------------------------
extern "C" void kernel_launch(void* const* d_in, const int* in_sizes, int n_in,
                              void* d_out, int out_size) {
    const float* x   = (const float*)d_in[0];
    const int*   row = (const int*)  d_in[1];
    const int*   col = (const int*)  d_in[2];
    const float* W1a = (const float*)d_in[3];
    const float* b1a = (const float*)d_in[4];
    const float* W1b = (const float*)d_in[5];
    const float* b1b = (const float*)d_in[6];
    const float* g1  = (const float*)d_in[7];
    const float* be1 = (const float*)d_in[8];
    const float* W2a = (const float*)d_in[9];
    const float* b2a = (const float*)d_in[10];
    const float* W2b = (const float*)d_in[11];
    const float* b2b = (const float*)d_in[12];
    const float* g2  = (const float*)d_in[13];
    const float* be2 = (const float*)d_in[14];
    const float* Wf1 = (const float*)d_in[15];
    const float* bf1 = (const float*)d_in[16];
    const float* Wf2 = (const float*)d_in[17];
    const float* bf2 = (const float*)d_in[18];
    float* out = (float*)d_out;

    float* stats; int* counts;
    cudaGetSymbolAddress((void**)&stats,  d_stats);
    cudaGetSymbolAddress((void**)&counts, d_counts);

    cudaMemsetAsync(stats,  0, sizeof(float) * 4 * HH, 0);
    cudaMemsetAsync(counts, 0, sizeof(int) * NN, 0);

    // K1: y = x @ W1a (independent of CSR build; runs first, overlaps nothing
    // but dominates — CSR kernels queue behind on same stream)
    cudaFuncSetAttribute(k_gemm1, cudaFuncAttributeMaxDynamicSharedMemorySize,
                         FF * HH * (int)sizeof(float));
    {
        int warps  = (NN + 3) / 4;
        int blocks = (warps + 7) / 8;
        k_gemm1<<<blocks, 256, FF * HH * sizeof(float), 0>>>(x, W1a);
    }

    // CSR build
    const int eblk = (EE + 255) / 256;
    k_hist   <<<eblk, 256, 0, 0>>>(row);
    k_scan1  <<<NB_SCAN, 256, 0, 0>>>();
    k_scan2  <<<1, 256, 0, 0>>>();
    k_scan3  <<<NB_SCAN, 256, 0, 0>>>();
    k_scatter<<<eblk, 256, 0, 0>>>(row, col);

    const int nblk = (NN + 31) / 32;  // 1563 blocks of 32 warps
    k_gin1<<<nblk, 1024, 0, 0>>>(b1a, W1b, b1b);
    k_gin2<<<nblk, 1024, 0, 0>>>(g1, be1, W2a, b2a, W2b, b2b);
    k_head<<<400, 256, 0, 0>>>(Wf1, bf1, Wf2, bf2, g2, be2, out);
}

// round 3
// speedup vs baseline: 1.3981x; 1.0529x over previous
#include <cuda_runtime.h>

#define NN 50000
#define EE 800000
#define FF 602
#define HH 32
#define CC 41
#define BN_EPS 1e-5f
#define FULLMASK 0xffffffffu
#define NB_SCAN ((NN + 255) / 256)   // 196

// ---------------- scratch (device globals) ----------------------------------
static __device__ float d_y  [NN * HH];   // x @ W1a
static __device__ float d_h1 [NN * HH];   // conv1 pre-BN
static __device__ float d_h2 [NN * HH];   // conv2 pre-BN
static __device__ float d_stats[4 * HH];  // sum1, sumsq1, sum2, sumsq2
static __device__ int   d_counts[NN];
static __device__ int   d_rowptr[NN];
static __device__ int   d_cursor[NN];
static __device__ int   d_colsorted[EE];
static __device__ int   d_bsum[256];

// ---------------- K1: y[N,32] = x[N,602] @ W1a[602,32] ---------------------
__global__ void k_gemm1(const float* __restrict__ x, const float* __restrict__ W1a) {
    extern __shared__ float Ws[];  // FF*HH floats
    for (int i = threadIdx.x; i < FF * HH; i += blockDim.x) Ws[i] = W1a[i];
    __syncthreads();

    const int lane = threadIdx.x & 31;
    const int gw   = (blockIdx.x * blockDim.x + threadIdx.x) >> 5;
    const int r0   = gw * 4;
    if (r0 >= NN) return;

    const bool v1 = (r0 + 1) < NN, v2 = (r0 + 2) < NN, v3 = (r0 + 3) < NN;
    const float* x0 = x + (size_t)r0 * FF;

    float acc0 = 0.f, acc1 = 0.f, acc2 = 0.f, acc3 = 0.f;

    constexpr int KB_MAIN = (FF / 32) * 32;  // 576
    int kb = 0;
    for (; kb < KB_MAIN; kb += 32) {
        float xv0 = x0[kb + lane];
        float xv1 = v1 ? x0[1 * FF + kb + lane] : 0.f;
        float xv2 = v2 ? x0[2 * FF + kb + lane] : 0.f;
        float xv3 = v3 ? x0[3 * FF + kb + lane] : 0.f;
#pragma unroll
        for (int j = 0; j < 32; j++) {
            float w = Ws[(kb + j) * HH + lane];
            acc0 += __shfl_sync(FULLMASK, xv0, j) * w;
            acc1 += __shfl_sync(FULLMASK, xv1, j) * w;
            acc2 += __shfl_sync(FULLMASK, xv2, j) * w;
            acc3 += __shfl_sync(FULLMASK, xv3, j) * w;
        }
    }
    {   // tail: 602 - 576 = 26
        constexpr int REM = FF - KB_MAIN;
        float xv0 = (lane < REM) ? x0[kb + lane] : 0.f;
        float xv1 = (v1 && lane < REM) ? x0[1 * FF + kb + lane] : 0.f;
        float xv2 = (v2 && lane < REM) ? x0[2 * FF + kb + lane] : 0.f;
        float xv3 = (v3 && lane < REM) ? x0[3 * FF + kb + lane] : 0.f;
#pragma unroll
        for (int j = 0; j < REM; j++) {
            float w = Ws[(kb + j) * HH + lane];
            acc0 += __shfl_sync(FULLMASK, xv0, j) * w;
            acc1 += __shfl_sync(FULLMASK, xv1, j) * w;
            acc2 += __shfl_sync(FULLMASK, xv2, j) * w;
            acc3 += __shfl_sync(FULLMASK, xv3, j) * w;
        }
    }
    d_y[(size_t)r0 * HH + lane] = acc0;
    if (v1) d_y[(size_t)(r0 + 1) * HH + lane] = acc1;
    if (v2) d_y[(size_t)(r0 + 2) * HH + lane] = acc2;
    if (v3) d_y[(size_t)(r0 + 3) * HH + lane] = acc3;
}

// ---------------- CSR build --------------------------------------------------
// 4 edges per thread, int4 loads. EE divisible by 4.
__global__ void k_hist(const int* __restrict__ row) {
    int t = blockIdx.x * 256 + threadIdx.x;
    int base = t * 4;
    if (base >= EE) return;
    int4 r4 = *(const int4*)(row + base);
    atomicAdd(&d_counts[r4.x], 1);
    atomicAdd(&d_counts[r4.y], 1);
    atomicAdd(&d_counts[r4.z], 1);
    atomicAdd(&d_counts[r4.w], 1);
}

__global__ void k_scan1() {  // per-block sums of counts; block 0 zeros stats
    if (blockIdx.x == 0 && threadIdx.x < 4 * HH) d_stats[threadIdx.x] = 0.f;
    __shared__ int sh[256];
    int i = blockIdx.x * 256 + threadIdx.x;
    int v = (i < NN) ? d_counts[i] : 0;
    sh[threadIdx.x] = v;
    __syncthreads();
    for (int off = 128; off > 0; off >>= 1) {
        if (threadIdx.x < off) sh[threadIdx.x] += sh[threadIdx.x + off];
        __syncthreads();
    }
    if (threadIdx.x == 0) d_bsum[blockIdx.x] = sh[0];
}

__global__ void k_scan3() {  // redundant bsum prefix + local scan -> rowptr/cursor
    __shared__ int shb[256];
    __shared__ int sh[256];
    int tid = threadIdx.x;

    // scan the 196 block sums (every block does it — cheap)
    int bv = (tid < NB_SCAN) ? d_bsum[tid] : 0;
    shb[tid] = bv;
    __syncthreads();
    for (int off = 1; off < 256; off <<= 1) {
        int t = (tid >= off) ? shb[tid - off] : 0;
        __syncthreads();
        shb[tid] += t;
        __syncthreads();
    }
    // exclusive prefix for this block
    int blk = blockIdx.x;
    int boff = shb[blk] - d_bsum[blk];
    __syncthreads();

    int i = blk * 256 + tid;
    int c = (i < NN) ? d_counts[i] : 0;
    sh[tid] = c;
    __syncthreads();
    for (int off = 1; off < 256; off <<= 1) {
        int t = (tid >= off) ? sh[tid - off] : 0;
        __syncthreads();
        sh[tid] += t;
        __syncthreads();
    }
    int start = boff + sh[tid] - c;
    if (i < NN) { d_rowptr[i] = start; d_cursor[i] = start; }
}

__global__ void k_scatter(const int* __restrict__ row, const int* __restrict__ col) {
    int t = blockIdx.x * 256 + threadIdx.x;
    int base = t * 4;
    if (base >= EE) return;
    int4 r4 = *(const int4*)(row + base);
    int4 c4 = *(const int4*)(col + base);
    int p0 = atomicAdd(&d_cursor[r4.x], 1);
    int p1 = atomicAdd(&d_cursor[r4.y], 1);
    int p2 = atomicAdd(&d_cursor[r4.z], 1);
    int p3 = atomicAdd(&d_cursor[r4.w], 1);
    d_colsorted[p0] = c4.x;
    d_colsorted[p1] = c4.y;
    d_colsorted[p2] = c4.z;
    d_colsorted[p3] = c4.w;
}

// ---------------- fused gather + MLP -----------------------------------------
__device__ __forceinline__ float gather_raw(const float* __restrict__ src,
                                            int s0, int deg, int lane) {
    float acc = 0.f;
    for (int e0 = 0; e0 < deg; e0 += 32) {
        int rem = deg - e0;
        if (rem > 32) rem = 32;
        int idx = (lane < rem) ? d_colsorted[s0 + e0 + lane] : 0;
        int j = 0;
        for (; j + 4 <= rem; j += 4) {
            int c0 = __shfl_sync(FULLMASK, idx, j);
            int c1 = __shfl_sync(FULLMASK, idx, j + 1);
            int c2 = __shfl_sync(FULLMASK, idx, j + 2);
            int c3 = __shfl_sync(FULLMASK, idx, j + 3);
            float v0 = src[(size_t)c0 * HH + lane];
            float v1 = src[(size_t)c1 * HH + lane];
            float v2 = src[(size_t)c2 * HH + lane];
            float v3 = src[(size_t)c3 * HH + lane];
            acc += v0; acc += v1; acc += v2; acc += v3;
        }
        for (; j < rem; j++) {
            int c = __shfl_sync(FULLMASK, idx, j);
            acc += src[(size_t)c * HH + lane];
        }
    }
    return acc;
}

// conv1: h1 = relu(y[n] + agg(y) + b1a) @ W1b + b1b ; stats1
__global__ void __launch_bounds__(1024) k_gin1(
    const float* __restrict__ ba, const float* __restrict__ Wb,
    const float* __restrict__ bb) {
    __shared__ float Wsb[HH * HH];
    __shared__ float red1[32][32];
    __shared__ float red2[32][32];
    for (int i = threadIdx.x; i < HH * HH; i += 1024) Wsb[i] = Wb[i];
    __syncthreads();

    const int lane = threadIdx.x & 31;
    const int warp = threadIdx.x >> 5;
    const int n = blockIdx.x * 32 + warp;

    float s = 0.f, sq = 0.f;
    if (n < NN) {
        int s0  = d_rowptr[n];
        int deg = d_counts[n];
        float acc = gather_raw(d_y, s0, deg, lane);
        float z = d_y[(size_t)n * HH + lane] + acc + ba[lane];
        z = fmaxf(z, 0.f);
        float o = bb[lane];
#pragma unroll
        for (int j = 0; j < HH; j++)
            o += __shfl_sync(FULLMASK, z, j) * Wsb[j * HH + lane];
        d_h1[(size_t)n * HH + lane] = o;
        s = o; sq = o * o;
    }
    red1[warp][lane] = s;
    red2[warp][lane] = sq;
    __syncthreads();
    if (warp == 0) {
        float t1 = 0.f, t2 = 0.f;
#pragma unroll
        for (int w = 0; w < 32; w++) { t1 += red1[w][lane]; t2 += red2[w][lane]; }
        atomicAdd(&d_stats[lane],      t1);
        atomicAdd(&d_stats[HH + lane], t2);
    }
}

// conv2: BN1 folded into reads; h2 = relu((g+agg)@W2a+b2a)@W2b+b2b ; stats2
__global__ void __launch_bounds__(1024) k_gin2(
    const float* __restrict__ g1, const float* __restrict__ be1,
    const float* __restrict__ Wa, const float* __restrict__ ba,
    const float* __restrict__ Wb, const float* __restrict__ bb) {
    __shared__ float Wsa[HH * HH];
    __shared__ float Wsb[HH * HH];
    __shared__ float red1[32][32];
    __shared__ float red2[32][32];
    for (int i = threadIdx.x; i < HH * HH; i += 1024) { Wsa[i] = Wa[i]; Wsb[i] = Wb[i]; }
    __syncthreads();

    const int lane = threadIdx.x & 31;
    const int warp = threadIdx.x >> 5;
    const int n = blockIdx.x * 32 + warp;

    float m = d_stats[lane] * (1.f / NN);
    float v = d_stats[HH + lane] * (1.f / NN) - m * m;
    float scale = g1[lane] * rsqrtf(v + BN_EPS);
    float shift = be1[lane] - m * scale;

    float s = 0.f, sq = 0.f;
    if (n < NN) {
        int s0  = d_rowptr[n];
        int deg = d_counts[n];
        float raw = gather_raw(d_h1, s0, deg, lane);
        raw += d_h1[(size_t)n * HH + lane];            // self
        float t = raw * scale + (float)(deg + 1) * shift;
        float u = ba[lane];
#pragma unroll
        for (int j = 0; j < HH; j++)
            u += __shfl_sync(FULLMASK, t, j) * Wsa[j * HH + lane];
        u = fmaxf(u, 0.f);
        float o = bb[lane];
#pragma unroll
        for (int j = 0; j < HH; j++)
            o += __shfl_sync(FULLMASK, u, j) * Wsb[j * HH + lane];
        d_h2[(size_t)n * HH + lane] = o;
        s = o; sq = o * o;
    }
    red1[warp][lane] = s;
    red2[warp][lane] = sq;
    __syncthreads();
    if (warp == 0) {
        float t1 = 0.f, t2 = 0.f;
#pragma unroll
        for (int w = 0; w < 32; w++) { t1 += red1[w][lane]; t2 += red2[w][lane]; }
        atomicAdd(&d_stats[2 * HH + lane], t1);
        atomicAdd(&d_stats[3 * HH + lane], t2);
    }
}

// ---------------- head: out = relu(bn2(h2)@Wf1+bf1)@Wf2+bf2 ------------------
__global__ void k_head(const float* __restrict__ Wf1, const float* __restrict__ bf1,
                       const float* __restrict__ Wf2, const float* __restrict__ bf2,
                       const float* __restrict__ g2, const float* __restrict__ be2,
                       float* __restrict__ outp) {
    __shared__ float Ws1[HH * HH];
    __shared__ float Ws2[HH * CC];
    for (int i = threadIdx.x; i < HH * HH; i += blockDim.x) Ws1[i] = Wf1[i];
    for (int i = threadIdx.x; i < HH * CC; i += blockDim.x) Ws2[i] = Wf2[i];
    __syncthreads();

    const int lane = threadIdx.x & 31;
    const int gw   = (blockIdx.x * blockDim.x + threadIdx.x) >> 5;
    const int nw   = (gridDim.x * blockDim.x) >> 5;

    float m = d_stats[2 * HH + lane] * (1.f / NN);
    float v = d_stats[3 * HH + lane] * (1.f / NN) - m * m;
    float scale = g2[lane] * rsqrtf(v + BN_EPS);
    float shift = be2[lane] - m * scale;

    const float bf1L = bf1[lane];
    const float b0 = bf2[lane];
    const float b1 = (lane < CC - HH) ? bf2[lane + HH] : 0.f;

    for (int r = gw; r < NN; r += nw) {
        float gv = d_h2[(size_t)r * HH + lane] * scale + shift;
        float z = bf1L;
#pragma unroll
        for (int j = 0; j < HH; j++)
            z += __shfl_sync(FULLMASK, gv, j) * Ws1[j * HH + lane];
        z = fmaxf(z, 0.f);

        float a0 = b0, a1 = b1;
#pragma unroll
        for (int j = 0; j < HH; j++) {
            float zj = __shfl_sync(FULLMASK, z, j);
            a0 += zj * Ws2[j * CC + lane];
            if (lane < CC - HH) a1 += zj * Ws2[j * CC + lane + HH];
        }
        outp[(size_t)r * CC + lane] = a0;
        if (lane < CC - HH) outp[(size_t)r * CC + lane + HH] = a1;
    }
}

// ---------------- launcher ----------------------------------------------------
extern "C" void kernel_launch(void* const* d_in, const int* in_sizes, int n_in,
                              void* d_out, int out_size) {
    const float* x   = (const float*)d_in[0];
    const int*   row = (const int*)  d_in[1];
    const int*   col = (const int*)  d_in[2];
    const float* W1a = (const float*)d_in[3];
    const float* b1a = (const float*)d_in[4];
    const float* W1b = (const float*)d_in[5];
    const float* b1b = (const float*)d_in[6];
    const float* g1  = (const float*)d_in[7];
    const float* be1 = (const float*)d_in[8];
    const float* W2a = (const float*)d_in[9];
    const float* b2a = (const float*)d_in[10];
    const float* W2b = (const float*)d_in[11];
    const float* b2b = (const float*)d_in[12];
    const float* g2  = (const float*)d_in[13];
    const float* be2 = (const float*)d_in[14];
    const float* Wf1 = (const float*)d_in[15];
    const float* bf1 = (const float*)d_in[16];
    const float* Wf2 = (const float*)d_in[17];
    const float* bf2 = (const float*)d_in[18];
    float* out = (float*)d_out;

    // one-time infra (created on the uncaptured correctness call)
    static cudaStream_t sA = nullptr;
    static cudaEvent_t  evFork = nullptr, evJoin = nullptr;
    static bool inited = false;
    if (!inited) {
        cudaStreamCreateWithFlags(&sA, cudaStreamNonBlocking);
        cudaEventCreateWithFlags(&evFork, cudaEventDisableTiming);
        cudaEventCreateWithFlags(&evJoin, cudaEventDisableTiming);
        cudaFuncSetAttribute(k_gemm1, cudaFuncAttributeMaxDynamicSharedMemorySize,
                             FF * HH * (int)sizeof(float));
        inited = true;
    }

    int* counts;
    cudaGetSymbolAddress((void**)&counts, d_counts);

    // ---- fork: gemm1 on sA, CSR build on main stream -----------------------
    cudaEventRecord(evFork, 0);
    cudaStreamWaitEvent(sA, evFork, 0);

    {
        int warps  = (NN + 3) / 4;
        int blocks = (warps + 7) / 8;
        k_gemm1<<<blocks, 256, FF * HH * sizeof(float), sA>>>(x, W1a);
    }

    cudaMemsetAsync(counts, 0, sizeof(int) * NN, 0);
    const int eblk4 = (EE / 4 + 255) / 256;
    k_hist   <<<eblk4, 256, 0, 0>>>(row);
    k_scan1  <<<NB_SCAN, 256, 0, 0>>>();
    k_scan3  <<<NB_SCAN, 256, 0, 0>>>();
    k_scatter<<<eblk4, 256, 0, 0>>>(row, col);

    // ---- join ----------------------------------------------------------------
    cudaEventRecord(evJoin, sA);
    cudaStreamWaitEvent(0, evJoin, 0);

    const int nblk = (NN + 31) / 32;  // 1563 blocks of 32 warps
    k_gin1<<<nblk, 1024, 0, 0>>>(b1a, W1b, b1b);
    k_gin2<<<nblk, 1024, 0, 0>>>(g1, be1, W2a, b2a, W2b, b2b);
    k_head<<<592, 256, 0, 0>>>(Wf1, bf1, Wf2, bf2, g2, be2, out);
}